// round 11
// baseline (speedup 1.0000x reference)
#include <cuda_runtime.h>
#include <cuda_bf16.h>
#include <float.h>

#define MAX_N 8192
#define BLOCK 256
#define ROWS_PER_BLOCK 8   // one row per warp
#define GRID (MAX_N / ROWS_PER_BLOCK)   // 1024 -> single wave at 7 blocks/SM

__device__ float        g_block_sum[GRID];
__device__ unsigned int g_done_count = 0;   // self-resets via atomicInc wrap

__global__ __launch_bounds__(BLOCK, 7)      // regs<=36 -> 7 blocks/SM -> 1 wave
void triplet_fused_kernel(const float* __restrict__ sim,
                          const int* __restrict__ targets,
                          const int* __restrict__ idx,
                          float* __restrict__ out,
                          int n) {
    __shared__ float s_loss[ROWS_PER_BLOCK];
    __shared__ unsigned int s_is_last;

    const int tid = threadIdx.x;
    const int wid = tid >> 5;
    const int lid = tid & 31;

    const int row = blockIdx.x * ROWS_PER_BLOCK + wid;
    const int my_t = targets[row];
    const int self_col = idx[row];
    const float* __restrict__ rp = sim + (size_t)self_col * (size_t)n;
    const int4* __restrict__ tp = reinterpret_cast<const int4*>(targets);

    const int n_groups = n >> 7;              // 64 groups of 128 elements
    const int g_self   = self_col >> 7;       // the one group containing self

    float pos =  FLT_MAX;
    float neg = -FLT_MAX;

    // Fast body: 1 compare per element, no self check (self can't be here).
    #define FAST_GROUP(IT)                                                    \
    do {                                                                      \
        const int j = (IT) * 128 + lid * 4;                                   \
        const float4 v = __ldcs(reinterpret_cast<const float4*>(rp + j));     \
        const int4   t = tp[j >> 2];                                          \
        if (t.x == my_t) pos = fminf(pos, v.x); else neg = fmaxf(neg, v.x);   \
        if (t.y == my_t) pos = fminf(pos, v.y); else neg = fmaxf(neg, v.y);   \
        if (t.z == my_t) pos = fminf(pos, v.z); else neg = fmaxf(neg, v.z);   \
        if (t.w == my_t) pos = fminf(pos, v.w); else neg = fmaxf(neg, v.w);   \
    } while (0)

    // Groups strictly before the self group.
    #pragma unroll 4
    for (int it = 0; it < g_self; it++) FAST_GROUP(it);

    // The single group containing the self column: full check.
    {
        const int j = g_self * 128 + lid * 4;
        const float4 v = __ldcs(reinterpret_cast<const float4*>(rp + j));
        const int4   t = tp[j >> 2];
        if (t.x == my_t) { if (j + 0 != self_col) pos = fminf(pos, v.x); }
        else             { neg = fmaxf(neg, v.x); }
        if (t.y == my_t) { if (j + 1 != self_col) pos = fminf(pos, v.y); }
        else             { neg = fmaxf(neg, v.y); }
        if (t.z == my_t) { if (j + 2 != self_col) pos = fminf(pos, v.z); }
        else             { neg = fmaxf(neg, v.z); }
        if (t.w == my_t) { if (j + 3 != self_col) pos = fminf(pos, v.w); }
        else             { neg = fmaxf(neg, v.w); }
    }

    // Groups strictly after the self group.
    #pragma unroll 4
    for (int it = g_self + 1; it < n_groups; it++) FAST_GROUP(it);

    #undef FAST_GROUP

    // Warp reduction.
    #pragma unroll
    for (int off = 16; off > 0; off >>= 1) {
        pos = fminf(pos, __shfl_xor_sync(0xFFFFFFFFu, pos, off));
        neg = fmaxf(neg, __shfl_xor_sync(0xFFFFFFFFu, neg, off));
    }
    if (lid == 0) s_loss[wid] = fmaxf(neg - pos + 0.1f, 0.0f);
    __syncthreads();

    // One thread sums the block's 8 losses in FIXED order -> deterministic.
    if (tid == 0) {
        float bs = 0.0f;
        #pragma unroll
        for (int w = 0; w < ROWS_PER_BLOCK; w++) bs += s_loss[w];
        g_block_sum[blockIdx.x] = bs;
        __threadfence();
        unsigned int prev = atomicInc(&g_done_count, GRID - 1);
        s_is_last = (prev == GRID - 1) ? 1u : 0u;
    }
    __syncthreads();

    // Last block reduces the 1024 partials in fixed tree order (deterministic).
    if (s_is_last) {
        __shared__ float s_sum[BLOCK / 32];
        const float4* bp = reinterpret_cast<const float4*>(g_block_sum);
        float4 a = __ldcg(bp + tid);
        float acc = (a.x + a.y) + (a.z + a.w);
        #pragma unroll
        for (int off = 16; off > 0; off >>= 1)
            acc += __shfl_xor_sync(0xFFFFFFFFu, acc, off);
        if (lid == 0) s_sum[wid] = acc;
        __syncthreads();
        if (wid == 0) {
            acc = (lid < BLOCK / 32) ? s_sum[lid] : 0.0f;
            #pragma unroll
            for (int off = 4; off > 0; off >>= 1)
                acc += __shfl_xor_sync(0xFFFFFFFFu, acc, off);
            if (lid == 0) out[0] = acc / (float)n;
        }
    }
}

extern "C" void kernel_launch(void* const* d_in, const int* in_sizes, int n_in,
                              void* d_out, int out_size) {
    const float* sim     = (const float*)d_in[0];
    const int*   targets = (const int*)d_in[1];
    const int*   idx     = (const int*)d_in[2];
    float* out = (float*)d_out;

    const int n = in_sizes[1];   // 8192

    triplet_fused_kernel<<<GRID, BLOCK>>>(sim, targets, idx, out, n);
}

// round 12
// speedup vs baseline: 1.0768x; 1.0768x over previous
#include <cuda_runtime.h>
#include <cuda_bf16.h>
#include <float.h>

#define MAX_N 8192
#define BLOCK 256
#define ROWS_PER_BLOCK 8   // one row per warp
#define GRID (MAX_N / ROWS_PER_BLOCK)   // 1024 -> single wave at 7 blocks/SM

__device__ float        g_block_sum[GRID];
__device__ unsigned int g_done_count = 0;   // self-resets via atomicInc wrap

__global__ __launch_bounds__(BLOCK, 7)      // regs<=36 -> 7 blocks/SM -> 1 wave
void triplet_fused_kernel(const float* __restrict__ sim,
                          const int* __restrict__ targets,
                          const int* __restrict__ idx,
                          float* __restrict__ out,
                          int n) {
    __shared__ float s_loss[ROWS_PER_BLOCK];
    __shared__ unsigned int s_is_last;

    const int tid = threadIdx.x;
    const int wid = tid >> 5;
    const int lid = tid & 31;

    const int row = blockIdx.x * ROWS_PER_BLOCK + wid;
    const int my_t = targets[row];
    const int self_col = idx[row];
    const float* __restrict__ rp = sim + (size_t)self_col * (size_t)n;
    const int4* __restrict__ tp = reinterpret_cast<const int4*>(targets);

    float pos =  FLT_MAX;
    float neg = -FLT_MAX;

    // Warp streams its 32 KB row (evict-first); targets are L1-resident.
    // FIXED trip count + unroll 4 -> ptxas front-batches 4 independent
    // LDG.128 pairs per thread (this batching is what sustains ~5.5 TB/s;
    // R11 proved dynamic bounds destroy it).
    #pragma unroll 4
    for (int it = 0; it < MAX_N / (32 * 4); it++) {
        const int j = it * 128 + lid * 4;
        const float4 v = __ldcs(reinterpret_cast<const float4*>(rp + j));
        const int4   t = tp[j >> 2];

        if (t.x == my_t) { if (j + 0 != self_col) pos = fminf(pos, v.x); }
        else             { neg = fmaxf(neg, v.x); }
        if (t.y == my_t) { if (j + 1 != self_col) pos = fminf(pos, v.y); }
        else             { neg = fmaxf(neg, v.y); }
        if (t.z == my_t) { if (j + 2 != self_col) pos = fminf(pos, v.z); }
        else             { neg = fmaxf(neg, v.z); }
        if (t.w == my_t) { if (j + 3 != self_col) pos = fminf(pos, v.w); }
        else             { neg = fmaxf(neg, v.w); }
    }

    // Warp reduction.
    #pragma unroll
    for (int off = 16; off > 0; off >>= 1) {
        pos = fminf(pos, __shfl_xor_sync(0xFFFFFFFFu, pos, off));
        neg = fmaxf(neg, __shfl_xor_sync(0xFFFFFFFFu, neg, off));
    }
    if (lid == 0) s_loss[wid] = fmaxf(neg - pos + 0.1f, 0.0f);
    __syncthreads();

    // One thread sums the block's 8 losses in FIXED order -> deterministic.
    if (tid == 0) {
        float bs = 0.0f;
        #pragma unroll
        for (int w = 0; w < ROWS_PER_BLOCK; w++) bs += s_loss[w];
        g_block_sum[blockIdx.x] = bs;
        __threadfence();
        unsigned int prev = atomicInc(&g_done_count, GRID - 1);
        s_is_last = (prev == GRID - 1) ? 1u : 0u;
    }
    __syncthreads();

    // Last block reduces the 1024 partials in fixed tree order (deterministic).
    if (s_is_last) {
        __shared__ float s_sum[BLOCK / 32];
        const float4* bp = reinterpret_cast<const float4*>(g_block_sum);
        float4 a = __ldcg(bp + tid);
        float acc = (a.x + a.y) + (a.z + a.w);
        #pragma unroll
        for (int off = 16; off > 0; off >>= 1)
            acc += __shfl_xor_sync(0xFFFFFFFFu, acc, off);
        if (lid == 0) s_sum[wid] = acc;
        __syncthreads();
        if (wid == 0) {
            acc = (lid < BLOCK / 32) ? s_sum[lid] : 0.0f;
            #pragma unroll
            for (int off = 4; off > 0; off >>= 1)
                acc += __shfl_xor_sync(0xFFFFFFFFu, acc, off);
            if (lid == 0) out[0] = acc / (float)n;
        }
    }
}

extern "C" void kernel_launch(void* const* d_in, const int* in_sizes, int n_in,
                              void* d_out, int out_size) {
    const float* sim     = (const float*)d_in[0];
    const int*   targets = (const int*)d_in[1];
    const int*   idx     = (const int*)d_in[2];
    float* out = (float*)d_out;

    const int n = in_sizes[1];   // 8192

    triplet_fused_kernel<<<GRID, BLOCK>>>(sim, targets, idx, out, n);
}

// round 13
// speedup vs baseline: 1.1362x; 1.0551x over previous
#include <cuda_runtime.h>
#include <cuda_bf16.h>
#include <float.h>

#define MAX_N 8192
#define BLOCK 256
#define ROWS_PER_BLOCK 8   // one row per warp
#define GRID (MAX_N / ROWS_PER_BLOCK)   // 1024 -> single wave at 7 blocks/SM

__device__ float        g_block_sum[GRID];
__device__ unsigned int g_done_count = 0;   // self-resets via atomicInc wrap

__global__ __launch_bounds__(BLOCK, 7)      // regs<=36 -> 7 blocks/SM -> 1 wave
void triplet_fused_kernel(const float* __restrict__ sim,
                          const int* __restrict__ targets,
                          const int* __restrict__ idx,
                          float* __restrict__ out,
                          int n) {
    __shared__ float s_loss[ROWS_PER_BLOCK];
    __shared__ unsigned int s_is_last;

    const int tid = threadIdx.x;
    const int wid = tid >> 5;
    const int lid = tid & 31;

    const int row = blockIdx.x * ROWS_PER_BLOCK + wid;
    const int my_t = targets[row];
    const int self_col = idx[row];
    const float* __restrict__ rp = sim + (size_t)self_col * (size_t)n;
    const int4* __restrict__ tp = reinterpret_cast<const int4*>(targets);

    float pos =  FLT_MAX;
    float neg = -FLT_MAX;

    // Warp streams its 32 KB row (evict-first); targets are L1-resident.
    // Fixed-shape unroll-4 loop: ptxas front-batches 4 independent LDG.128
    // pairs per thread. This exact form is the measured optimum (49.66 us);
    // every structural deviation tried (R6-R12) was equal or worse.
    #pragma unroll 4
    for (int it = 0; it < n / (32 * 4); it++) {
        const int j = it * 128 + lid * 4;
        const float4 v = __ldcs(reinterpret_cast<const float4*>(rp + j));
        const int4   t = tp[j >> 2];

        if (t.x == my_t) { if (j + 0 != self_col) pos = fminf(pos, v.x); }
        else             { neg = fmaxf(neg, v.x); }
        if (t.y == my_t) { if (j + 1 != self_col) pos = fminf(pos, v.y); }
        else             { neg = fmaxf(neg, v.y); }
        if (t.z == my_t) { if (j + 2 != self_col) pos = fminf(pos, v.z); }
        else             { neg = fmaxf(neg, v.z); }
        if (t.w == my_t) { if (j + 3 != self_col) pos = fminf(pos, v.w); }
        else             { neg = fmaxf(neg, v.w); }
    }

    // Warp reduction.
    #pragma unroll
    for (int off = 16; off > 0; off >>= 1) {
        pos = fminf(pos, __shfl_xor_sync(0xFFFFFFFFu, pos, off));
        neg = fmaxf(neg, __shfl_xor_sync(0xFFFFFFFFu, neg, off));
    }
    if (lid == 0) s_loss[wid] = fmaxf(neg - pos + 0.1f, 0.0f);
    __syncthreads();

    // One thread sums the block's 8 losses in FIXED order -> deterministic.
    if (tid == 0) {
        float bs = 0.0f;
        #pragma unroll
        for (int w = 0; w < ROWS_PER_BLOCK; w++) bs += s_loss[w];
        g_block_sum[blockIdx.x] = bs;
        __threadfence();
        unsigned int prev = atomicInc(&g_done_count, GRID - 1);
        s_is_last = (prev == GRID - 1) ? 1u : 0u;
    }
    __syncthreads();

    // Last block reduces the 1024 partials in fixed tree order (deterministic).
    if (s_is_last) {
        __shared__ float s_sum[BLOCK / 32];
        const float4* bp = reinterpret_cast<const float4*>(g_block_sum);
        float4 a = __ldcg(bp + tid);
        float acc = (a.x + a.y) + (a.z + a.w);
        #pragma unroll
        for (int off = 16; off > 0; off >>= 1)
            acc += __shfl_xor_sync(0xFFFFFFFFu, acc, off);
        if (lid == 0) s_sum[wid] = acc;
        __syncthreads();
        if (wid == 0) {
            acc = (lid < BLOCK / 32) ? s_sum[lid] : 0.0f;
            #pragma unroll
            for (int off = 4; off > 0; off >>= 1)
                acc += __shfl_xor_sync(0xFFFFFFFFu, acc, off);
            if (lid == 0) out[0] = acc / (float)n;
        }
    }
}

extern "C" void kernel_launch(void* const* d_in, const int* in_sizes, int n_in,
                              void* d_out, int out_size) {
    const float* sim     = (const float*)d_in[0];
    const int*   targets = (const int*)d_in[1];
    const int*   idx     = (const int*)d_in[2];
    float* out = (float*)d_out;

    const int n = in_sizes[1];   // 8192

    triplet_fused_kernel<<<GRID, BLOCK>>>(sim, targets, idx, out, n);
}